// round 1
// baseline (speedup 1.0000x reference)
#include <cuda_runtime.h>
#include <cuda_bf16.h>

#define CIN  256
#define COUT 256
#define HDIM 64
#define WDIM 64
#define HW   4096
#define BATCH 8

// Scratch for q, k, v  (32MB each) — static device globals (alloc-free rule).
__device__ float g_q[(size_t)BATCH * COUT * HW];
__device__ float g_k[(size_t)BATCH * COUT * HW];
__device__ float g_v[(size_t)BATCH * COUT * HW];

// ---------------------------------------------------------------------------
// GEMM: C[o, p] = sum_i W[o,i] * X[i, p], per batch image.
//   X layout: [B, CIN, H, W] -> column p=(b,hw), element at b*CIN*HW + i*HW + hw
//   C layout: [B, COUT, H, W]
// 128x128 tile, BK=8, 256 threads, 8x8 micro-tile.
// blockIdx.z selects which of the 3 GEMMs (q / k / v).
// ---------------------------------------------------------------------------
__global__ __launch_bounds__(256)
void qkv_gemm_kernel(const float* __restrict__ wq,
                     const float* __restrict__ wk,
                     const float* __restrict__ wv,
                     const float* __restrict__ x,
                     const float* __restrict__ y)
{
    const int z = blockIdx.z;
    const float* Wmat = (z == 0) ? wq : (z == 1 ? wk : wv);
    const float* X    = (z == 0) ? y  : x;
    float*       C    = (z == 0) ? g_q : (z == 1 ? g_k : g_v);

    const int n0  = blockIdx.x * 128;        // pixel-column tile start
    const int m0  = blockIdx.y * 128;        // output-channel tile start
    const int b   = n0 >> 12;                // n0 / 4096
    const int hw0 = n0 & 4095;

    const float* Xb = X + (size_t)b * CIN * HW + hw0;
    float*       Cb = C + (size_t)b * COUT * HW + hw0;

    __shared__ float As[8][128];             // As[k][m]
    __shared__ float Bs[8][128];             // Bs[k][n]

    const int t  = threadIdx.x;
    const int tx = t & 15;                   // 0..15
    const int ty = t >> 4;                   // 0..15

    const int arow = t >> 1;                 // 0..127
    const int acol = (t & 1) * 4;            // 0 or 4
    const int brow = t >> 5;                 // 0..7
    const int bcol = (t & 31) * 4;           // 0..124

    float acc[8][8];
    #pragma unroll
    for (int i = 0; i < 8; i++)
        #pragma unroll
        for (int j = 0; j < 8; j++)
            acc[i][j] = 0.0f;

    for (int k0 = 0; k0 < CIN; k0 += 8) {
        // Load A tile (transposed into As[k][m])
        float4 a4 = *(const float4*)(Wmat + (size_t)(m0 + arow) * CIN + k0 + acol);
        As[acol + 0][arow] = a4.x;
        As[acol + 1][arow] = a4.y;
        As[acol + 2][arow] = a4.z;
        As[acol + 3][arow] = a4.w;

        // Load B tile (row-contiguous)
        float4 b4 = *(const float4*)(Xb + (size_t)(k0 + brow) * HW + bcol);
        *(float4*)&Bs[brow][bcol] = b4;

        __syncthreads();

        #pragma unroll
        for (int kk = 0; kk < 8; kk++) {
            float a[8], bb[8];
            *(float4*)(a)      = *(const float4*)&As[kk][ty * 4];
            *(float4*)(a + 4)  = *(const float4*)&As[kk][64 + ty * 4];
            *(float4*)(bb)     = *(const float4*)&Bs[kk][tx * 4];
            *(float4*)(bb + 4) = *(const float4*)&Bs[kk][64 + tx * 4];
            #pragma unroll
            for (int i = 0; i < 8; i++)
                #pragma unroll
                for (int j = 0; j < 8; j++)
                    acc[i][j] = fmaf(a[i], bb[j], acc[i][j]);
        }
        __syncthreads();
    }

    // Epilogue: rows m0 + {ty*4+i, 64+ty*4+i}, cols n0 + {tx*4+j, 64+tx*4+j}
    #pragma unroll
    for (int i = 0; i < 8; i++) {
        int mi = (i < 4) ? (ty * 4 + i) : (64 + ty * 4 + (i - 4));
        float* crow = Cb + (size_t)(m0 + mi) * HW;
        *(float4*)(crow + tx * 4)      = make_float4(acc[i][0], acc[i][1], acc[i][2], acc[i][3]);
        *(float4*)(crow + 64 + tx * 4) = make_float4(acc[i][4], acc[i][5], acc[i][6], acc[i][7]);
    }
}

// ---------------------------------------------------------------------------
// Window attention epilogue.
// For each (b,c,h,w): gather 3x3 window of k,v (out-of-bounds -> 0, which is
// exactly what the reference's zero-padded conv produces), add rel bias,
// per-element softmax over the 9 logits q*(k+bias), weighted sum with v.
// ---------------------------------------------------------------------------
__global__ __launch_bounds__(256)
void attn_kernel(const float* __restrict__ rel_h,
                 const float* __restrict__ rel_w,
                 float* __restrict__ out)
{
    const int w = threadIdx.x & 63;
    const int h = (blockIdx.x << 2) + (threadIdx.x >> 6);
    const int c = blockIdx.y;
    const int b = blockIdx.z;

    const size_t plane = ((size_t)b * COUT + c) * HW;
    const int    hw    = h * WDIM + w;

    const float qv = g_q[plane + hw];

    // Bias: channels [0,128): rel_h[c*3 + di]  (depends on di only)
    //       channels [128,256): rel_w[(c-128)*3 + dj] (depends on dj only)
    float bias3[3];
    if (c < 128) {
        bias3[0] = rel_h[c * 3 + 0];
        bias3[1] = rel_h[c * 3 + 1];
        bias3[2] = rel_h[c * 3 + 2];
    } else {
        bias3[0] = rel_w[(c - 128) * 3 + 0];
        bias3[1] = rel_w[(c - 128) * 3 + 1];
        bias3[2] = rel_w[(c - 128) * 3 + 2];
    }
    const bool use_h = (c < 128);

    float lg[9], vv[9];
    float mx = -1e30f;
    int idx = 0;
    #pragma unroll
    for (int di = 0; di < 3; di++) {
        const int hh = h + di - 1;
        const bool hok = ((unsigned)hh < (unsigned)HDIM);
        #pragma unroll
        for (int dj = 0; dj < 3; dj++) {
            const int ww = w + dj - 1;
            const bool ok = hok && ((unsigned)ww < (unsigned)WDIM);
            float kv = 0.0f, vval = 0.0f;
            if (ok) {
                const size_t off = plane + hh * WDIM + ww;
                kv   = g_k[off];
                vval = g_v[off];
            }
            const float bias = use_h ? bias3[di] : bias3[dj];
            const float l = qv * (kv + bias);
            lg[idx] = l;
            vv[idx] = vval;
            mx = fmaxf(mx, l);
            idx++;
        }
    }

    float den = 0.0f, num = 0.0f;
    #pragma unroll
    for (int i = 0; i < 9; i++) {
        const float e = __expf(lg[i] - mx);
        den += e;
        num = fmaf(e, vv[i], num);
    }

    out[plane + hw] = num / den;
}

// ---------------------------------------------------------------------------
// Launch
// ---------------------------------------------------------------------------
extern "C" void kernel_launch(void* const* d_in, const int* in_sizes, int n_in,
                              void* d_out, int out_size)
{
    const float* x     = (const float*)d_in[0];
    const float* y     = (const float*)d_in[1];
    const float* wq    = (const float*)d_in[2];
    const float* wk    = (const float*)d_in[3];
    const float* wv    = (const float*)d_in[4];
    const float* rel_h = (const float*)d_in[5];
    const float* rel_w = (const float*)d_in[6];
    float* out = (float*)d_out;

    // 3 GEMMs in one grid: z=0 -> q(wq,y), z=1 -> k(wk,x), z=2 -> v(wv,x)
    dim3 ggrid(BATCH * HW / 128, COUT / 128, 3);   // (256, 2, 3)
    qkv_gemm_kernel<<<ggrid, 256>>>(wq, wk, wv, x, y);

    dim3 agrid(HDIM / 4, COUT, BATCH);             // (16, 256, 8)
    attn_kernel<<<agrid, 256>>>(rel_h, rel_w, out);
}

// round 3
// speedup vs baseline: 2.3244x; 2.3244x over previous
#include <cuda_runtime.h>
#include <cuda_bf16.h>
#include <cstdint>

#define CIN  256
#define COUT 256
#define HDIM 64
#define WDIM 64
#define HW   4096
#define BATCH 8

// Scratch for q, k, v (33.5MB each) — static device globals (alloc-free rule).
__device__ float g_q[(size_t)BATCH * COUT * HW];
__device__ float g_k[(size_t)BATCH * COUT * HW];
__device__ float g_v[(size_t)BATCH * COUT * HW];

// ---------------------------------------------------------------------------
// helpers
// ---------------------------------------------------------------------------
// fp32 pair -> packed bf16x2 (lower 16 bits = a, upper = b)
__device__ __forceinline__ uint32_t f2bf2(float a, float b) {
    uint32_t r;
    asm("cvt.rn.satfinite.bf16x2.f32 %0, %1, %2;" : "=r"(r) : "f"(b), "f"(a));
    return r;
}

#define LDSM_X4(r0, r1, r2, r3, addr)                                           \
    asm volatile("ldmatrix.sync.aligned.m8n8.x4.shared.b16 {%0,%1,%2,%3}, [%4];"\
                 : "=r"(r0), "=r"(r1), "=r"(r2), "=r"(r3) : "r"(addr))

#define LDSM_X4_T(r0, r1, r2, r3, addr)                                         \
    asm volatile("ldmatrix.sync.aligned.m8n8.x4.trans.shared.b16 {%0,%1,%2,%3}, [%4];"\
                 : "=r"(r0), "=r"(r1), "=r"(r2), "=r"(r3) : "r"(addr))

#define MMA16816(d, a, b0, b1)                                                  \
    asm volatile("mma.sync.aligned.m16n8k16.row.col.f32.bf16.bf16.f32 "         \
        "{%0,%1,%2,%3}, {%4,%5,%6,%7}, {%8,%9}, {%0,%1,%2,%3};"                 \
        : "+f"((d)[0]), "+f"((d)[1]), "+f"((d)[2]), "+f"((d)[3])                \
        : "r"((a)[0]), "r"((a)[1]), "r"((a)[2]), "r"((a)[3]),                   \
          "r"(b0), "r"(b1))

#define A_STRIDE 40     // bf16 elems per row (128x32 tile, padded)
#define B_STRIDE 136    // bf16 elems per row (32x128 tile, padded)

// ---------------------------------------------------------------------------
// GEMM: C[o,p] = sum_i W[o,i] * X[i,p] per batch image, fp32 via bf16 3-split.
// Block tile 128(M) x 128(N), K-blocks of 32. 256 threads, 8 warps (32x64 each).
// blockIdx.z: 0 = q(wq,y), 1 = k(wk,x), 2 = v(wv,x).
// ---------------------------------------------------------------------------
__global__ __launch_bounds__(256)
void qkv_gemm_mma(const float* __restrict__ wq, const float* __restrict__ wk,
                  const float* __restrict__ wv, const float* __restrict__ x,
                  const float* __restrict__ y)
{
    __shared__ __align__(16) __nv_bfloat16 Ah[128 * A_STRIDE];
    __shared__ __align__(16) __nv_bfloat16 Al[128 * A_STRIDE];
    __shared__ __align__(16) __nv_bfloat16 Bh[32 * B_STRIDE];
    __shared__ __align__(16) __nv_bfloat16 Bl[32 * B_STRIDE];

    const int z = blockIdx.z;
    const float* Wm = (z == 0) ? wq : (z == 1 ? wk : wv);
    const float* X  = (z == 0) ? y : x;
    float*       C  = (z == 0) ? g_q : (z == 1 ? g_k : g_v);

    const int n0  = blockIdx.x * 128;
    const int m0  = blockIdx.y * 128;
    const int b   = n0 >> 12;
    const int hw0 = n0 & 4095;
    const float* Xb = X + (size_t)b * CIN * HW + hw0;
    float*       Cb = C + (size_t)b * COUT * HW + hw0;

    const int tid  = threadIdx.x;
    const int lane = tid & 31;
    const int wid  = tid >> 5;
    const int wm   = (wid >> 1) * 32;   // warp m offset (0,32,64,96)
    const int wn   = (wid & 1) * 64;    // warp n offset (0,64)

    float acc[2][8][4];
    #pragma unroll
    for (int i = 0; i < 2; i++)
        #pragma unroll
        for (int j = 0; j < 8; j++)
            #pragma unroll
            for (int q = 0; q < 4; q++)
                acc[i][j][q] = 0.0f;

    // SMEM base addresses (u32, shared window)
    const uint32_t sAh = (uint32_t)__cvta_generic_to_shared(Ah);
    const uint32_t sAl = (uint32_t)__cvta_generic_to_shared(Al);
    const uint32_t sBh = (uint32_t)__cvta_generic_to_shared(Bh);
    const uint32_t sBl = (uint32_t)__cvta_generic_to_shared(Bl);

    for (int k0 = 0; k0 < CIN; k0 += 32) {
        // ---- Load A: W[m0..+127][k0..+31] fp32, split to bf16 hi/lo ----
        {
            const int col = (tid & 7) * 4;        // 0..28
            #pragma unroll
            for (int i = 0; i < 4; i++) {
                const int row = (tid >> 3) + i * 32;
                const float4 a = *(const float4*)(Wm + (size_t)(m0 + row) * CIN + k0 + col);
                const uint32_t h01 = f2bf2(a.x, a.y);
                const uint32_t h23 = f2bf2(a.z, a.w);
                const float r0 = a.x - __int_as_float(h01 << 16);
                const float r1 = a.y - __int_as_float(h01 & 0xFFFF0000u);
                const float r2 = a.z - __int_as_float(h23 << 16);
                const float r3 = a.w - __int_as_float(h23 & 0xFFFF0000u);
                __nv_bfloat16* ph = Ah + row * A_STRIDE + col;
                __nv_bfloat16* pl = Al + row * A_STRIDE + col;
                ((uint32_t*)ph)[0] = h01;
                ((uint32_t*)ph)[1] = h23;
                ((uint32_t*)pl)[0] = f2bf2(r0, r1);
                ((uint32_t*)pl)[1] = f2bf2(r2, r3);
            }
        }
        // ---- Load B: X[k0..+31][n0..+127] fp32, split to bf16 hi/lo ----
        {
            const int col = (tid & 31) * 4;       // 0..124
            #pragma unroll
            for (int i = 0; i < 4; i++) {
                const int k = (tid >> 5) + i * 8;
                const float4 v = *(const float4*)(Xb + (size_t)(k0 + k) * HW + col);
                const uint32_t h01 = f2bf2(v.x, v.y);
                const uint32_t h23 = f2bf2(v.z, v.w);
                const float r0 = v.x - __int_as_float(h01 << 16);
                const float r1 = v.y - __int_as_float(h01 & 0xFFFF0000u);
                const float r2 = v.z - __int_as_float(h23 << 16);
                const float r3 = v.w - __int_as_float(h23 & 0xFFFF0000u);
                __nv_bfloat16* ph = Bh + k * B_STRIDE + col;
                __nv_bfloat16* pl = Bl + k * B_STRIDE + col;
                ((uint32_t*)ph)[0] = h01;
                ((uint32_t*)ph)[1] = h23;
                ((uint32_t*)pl)[0] = f2bf2(r0, r1);
                ((uint32_t*)pl)[1] = f2bf2(r2, r3);
            }
        }
        __syncthreads();

        // ---- Compute: 2 ksteps of 16 ----
        #pragma unroll
        for (int ks = 0; ks < 2; ks++) {
            const int kb = ks * 16;
            uint32_t ah[2][4], al[2][4];
            #pragma unroll
            for (int mt = 0; mt < 2; mt++) {
                const uint32_t off =
                    (uint32_t)((wm + mt * 16 + (lane & 15)) * A_STRIDE + kb + (lane >> 4) * 8) * 2;
                LDSM_X4(ah[mt][0], ah[mt][1], ah[mt][2], ah[mt][3], sAh + off);
                LDSM_X4(al[mt][0], al[mt][1], al[mt][2], al[mt][3], sAl + off);
            }
            #pragma unroll
            for (int ntp = 0; ntp < 4; ntp++) {       // each covers n16
                const int nb = wn + ntp * 16;
                const uint32_t off =
                    (uint32_t)((kb + (lane & 15)) * B_STRIDE + nb + (lane >> 4) * 8) * 2;
                uint32_t bh[4], bl[4];
                LDSM_X4_T(bh[0], bh[1], bh[2], bh[3], sBh + off);
                LDSM_X4_T(bl[0], bl[1], bl[2], bl[3], sBl + off);
                #pragma unroll
                for (int mt = 0; mt < 2; mt++) {
                    #pragma unroll
                    for (int h2 = 0; h2 < 2; h2++) {
                        float* d = acc[mt][ntp * 2 + h2];
                        MMA16816(d, ah[mt], bh[h2 * 2], bh[h2 * 2 + 1]);
                        MMA16816(d, al[mt], bh[h2 * 2], bh[h2 * 2 + 1]);
                        MMA16816(d, ah[mt], bl[h2 * 2], bl[h2 * 2 + 1]);
                    }
                }
            }
        }
        __syncthreads();
    }

    // ---- Epilogue ----
    #pragma unroll
    for (int mt = 0; mt < 2; mt++) {
        const int m = wm + mt * 16 + (lane >> 2);
        #pragma unroll
        for (int nt = 0; nt < 8; nt++) {
            const int n = wn + nt * 8 + (lane & 3) * 2;
            const float* d = acc[mt][nt];
            *(float2*)(Cb + (size_t)(m0 + m) * HW + n)     = make_float2(d[0], d[1]);
            *(float2*)(Cb + (size_t)(m0 + m + 8) * HW + n) = make_float2(d[2], d[3]);
        }
    }
}

// ---------------------------------------------------------------------------
// Window attention: SMEM-tiled, 4 px/thread, zero halo, safe max-subtraction.
// Block = (h-strip of 16, c, b); 256 threads.
// ---------------------------------------------------------------------------
__global__ __launch_bounds__(256)
void attn_kernel2(const float* __restrict__ rel_h, const float* __restrict__ rel_w,
                  float* __restrict__ out)
{
    __shared__ float Ks[18][68];
    __shared__ float Vs[18][68];

    const int tid = threadIdx.x;
    const int h0  = blockIdx.x * 16;
    const int c   = blockIdx.y;
    const int b   = blockIdx.z;
    const size_t plane = ((size_t)b * COUT + c) * HW;
    const float* kp = g_k + plane;
    const float* vp = g_v + plane;

    // Fill 18 rows x cols [-1..64] (j = w+1). OOB -> 0 (matches zero padding).
    for (int i = tid; i < 18 * 16; i += 256) {
        const int r = i >> 4, f4 = i & 15;
        const int gh = h0 - 1 + r;
        float4 kv = make_float4(0.f, 0.f, 0.f, 0.f);
        float4 vv = make_float4(0.f, 0.f, 0.f, 0.f);
        if ((unsigned)gh < (unsigned)HDIM) {
            kv = *(const float4*)(kp + gh * WDIM + f4 * 4);
            vv = *(const float4*)(vp + gh * WDIM + f4 * 4);
        }
        const int j = f4 * 4 + 1;
        Ks[r][j] = kv.x; Ks[r][j + 1] = kv.y; Ks[r][j + 2] = kv.z; Ks[r][j + 3] = kv.w;
        Vs[r][j] = vv.x; Vs[r][j + 1] = vv.y; Vs[r][j + 2] = vv.z; Vs[r][j + 3] = vv.w;
    }
    if (tid < 18) {
        Ks[tid][0] = 0.f; Ks[tid][65] = 0.f;
        Vs[tid][0] = 0.f; Vs[tid][65] = 0.f;
    }

    float bias[3];
    const bool use_h = (c < 128);
    if (use_h) {
        bias[0] = rel_h[c * 3 + 0]; bias[1] = rel_h[c * 3 + 1]; bias[2] = rel_h[c * 3 + 2];
    } else {
        bias[0] = rel_w[(c - 128) * 3 + 0]; bias[1] = rel_w[(c - 128) * 3 + 1];
        bias[2] = rel_w[(c - 128) * 3 + 2];
    }
    __syncthreads();

    const int lr = tid >> 4;            // local row 0..15
    const int w0 = (tid & 15) * 4;      // 0..60
    const int h  = h0 + lr;

    const float4 q4 = *(const float4*)(g_q + plane + h * WDIM + w0);
    const float q[4] = {q4.x, q4.y, q4.z, q4.w};

    // Stage the 3 k/v row segments (6 wide) in registers.
    float kk[3][6], vv[3][6];
    #pragma unroll
    for (int dr = 0; dr < 3; dr++) {
        const float* krow = &Ks[lr + dr][w0];
        const float* vrow = &Vs[lr + dr][w0];
        const float4 ka = *(const float4*)krow;
        const float2 kb = *(const float2*)(krow + 4);
        const float4 va = *(const float4*)vrow;
        const float2 vb = *(const float2*)(vrow + 4);
        kk[dr][0] = ka.x; kk[dr][1] = ka.y; kk[dr][2] = ka.z;
        kk[dr][3] = ka.w; kk[dr][4] = kb.x; kk[dr][5] = kb.y;
        vv[dr][0] = va.x; vv[dr][1] = va.y; vv[dr][2] = va.z;
        vv[dr][3] = va.w; vv[dr][4] = vb.x; vv[dr][5] = vb.y;
    }

    float res[4];
    #pragma unroll
    for (int p = 0; p < 4; p++) {
        float lg[9];
        float mx = -1e30f;
        #pragma unroll
        for (int dr = 0; dr < 3; dr++)
            #pragma unroll
            for (int dj = 0; dj < 3; dj++) {
                const float bb = use_h ? bias[dr] : bias[dj];
                const float l = q[p] * (kk[dr][p + dj] + bb);
                lg[dr * 3 + dj] = l;
                mx = fmaxf(mx, l);
            }
        float den = 0.f, num = 0.f;
        #pragma unroll
        for (int dr = 0; dr < 3; dr++)
            #pragma unroll
            for (int dj = 0; dj < 3; dj++) {
                const float e = __expf(lg[dr * 3 + dj] - mx);
                den += e;
                num = fmaf(e, vv[dr][p + dj], num);
            }
        res[p] = __fdividef(num, den);
    }

    *(float4*)(out + plane + h * WDIM + w0) = make_float4(res[0], res[1], res[2], res[3]);
}

// ---------------------------------------------------------------------------
extern "C" void kernel_launch(void* const* d_in, const int* in_sizes, int n_in,
                              void* d_out, int out_size)
{
    const float* x     = (const float*)d_in[0];
    const float* y     = (const float*)d_in[1];
    const float* wq    = (const float*)d_in[2];
    const float* wk    = (const float*)d_in[3];
    const float* wv    = (const float*)d_in[4];
    const float* rel_h = (const float*)d_in[5];
    const float* rel_w = (const float*)d_in[6];
    float* out = (float*)d_out;

    dim3 ggrid(BATCH * HW / 128, COUT / 128, 3);   // (256, 2, 3)
    qkv_gemm_mma<<<ggrid, 256>>>(wq, wk, wv, x, y);

    dim3 agrid(HDIM / 16, COUT, BATCH);            // (4, 256, 8)
    attn_kernel2<<<agrid, 256>>>(rel_h, rel_w, out);
}